// round 16
// baseline (speedup 1.0000x reference)
#include <cuda_runtime.h>
#include <cuda_bf16.h>
#include <cuda_fp16.h>
#include <cstdint>

// Problem constants
#define BB 2
#define SS 2048
#define EE 1024
#define HH 16
#define DD 64
#define MM (BB * SS)   // 4096

// ---------------- scratch (device globals; no allocation allowed) ----------
__device__ __half g_xh[MM * EE];             // fp16 copy of x [4096,1024]
__device__ __half g_Wqh[EE * EE];
__device__ __half g_Wkh[EE * EE];
__device__ __half g_Wvh[EE * EE];
__device__ __half g_Woh[EE * EE];
__device__ __half g_Qh[BB * HH * SS * DD];   // [b,h,s,d] fp16 (pre-scaled)
__device__ __half g_Kh[BB * HH * SS * DD];
__device__ __half g_Vh[BB * HH * SS * DD];
__device__ __half g_ctxh[BB * SS * EE];      // [b,s,e] fp16

// ======================= helpers ===========================================
__device__ __forceinline__ uint32_t smem_u32(const void* p) {
    uint32_t a;
    asm("{ .reg .u64 t; cvta.to.shared.u64 t, %1; cvt.u32.u64 %0, t; }" : "=r"(a) : "l"(p));
    return a;
}

#define CP_ASYNC16(saddr, gptr) \
    asm volatile("cp.async.cg.shared.global [%0], [%1], 16;" \
                 :: "r"(saddr), "l"(gptr) : "memory")
#define CP_COMMIT() asm volatile("cp.async.commit_group;" ::: "memory")
#define CP_WAIT0()  asm volatile("cp.async.wait_group 0;" ::: "memory")
#define CP_WAIT1()  asm volatile("cp.async.wait_group 1;" ::: "memory")
#define CP_WAIT2()  asm volatile("cp.async.wait_group 2;" ::: "memory")

#define LDSM_X4(r, addr) \
    asm volatile("ldmatrix.sync.aligned.m8n8.x4.shared.b16 {%0,%1,%2,%3}, [%4];" \
        : "=r"((r)[0]), "=r"((r)[1]), "=r"((r)[2]), "=r"((r)[3]) : "r"(addr))

#define LDSM_T_X4(r, addr) \
    asm volatile("ldmatrix.sync.aligned.m8n8.x4.trans.shared.b16 {%0,%1,%2,%3}, [%4];" \
        : "=r"((r)[0]), "=r"((r)[1]), "=r"((r)[2]), "=r"((r)[3]) : "r"(addr))

__device__ __forceinline__ void mma16816h(float* c, const uint32_t* a,
                                          uint32_t b0, uint32_t b1) {
    asm volatile(
        "mma.sync.aligned.m16n8k16.row.col.f32.f16.f16.f32 "
        "{%0,%1,%2,%3}, {%4,%5,%6,%7}, {%8,%9}, {%0,%1,%2,%3};"
        : "+f"(c[0]), "+f"(c[1]), "+f"(c[2]), "+f"(c[3])
        : "r"(a[0]), "r"(a[1]), "r"(a[2]), "r"(a[3]), "r"(b0), "r"(b1));
}

__device__ __forceinline__ uint32_t ex2_h2(uint32_t u) {
    asm("ex2.approx.f16x2 %0, %1;" : "=r"(u) : "r"(u));
    return u;
}

// ================ fp32 -> fp16 convert passes ===============================
__global__ __launch_bounds__(256) void cvt_f2h_kernel(
    const float* __restrict__ src, __half* __restrict__ dst, int n)
{
    const int i = (blockIdx.x * 256 + threadIdx.x) * 8;
    if (i >= n) return;
    float4 a = *reinterpret_cast<const float4*>(src + i);
    float4 b = *reinterpret_cast<const float4*>(src + i + 4);
    __half2 h0 = __floats2half2_rn(a.x, a.y);
    __half2 h1 = __floats2half2_rn(a.z, a.w);
    __half2 h2 = __floats2half2_rn(b.x, b.y);
    __half2 h3 = __floats2half2_rn(b.z, b.w);
    uint4 o;
    o.x = *reinterpret_cast<uint32_t*>(&h0);
    o.y = *reinterpret_cast<uint32_t*>(&h1);
    o.z = *reinterpret_cast<uint32_t*>(&h2);
    o.w = *reinterpret_cast<uint32_t*>(&h3);
    *reinterpret_cast<uint4*>(dst + i) = o;
}

__global__ __launch_bounds__(256) void cvt_w_kernel(
    const float* __restrict__ s0, const float* __restrict__ s1,
    const float* __restrict__ s2, const float* __restrict__ s3,
    __half* __restrict__ d0, __half* __restrict__ d1,
    __half* __restrict__ d2, __half* __restrict__ d3)
{
    const int z = blockIdx.y;
    const float* src = (z == 0) ? s0 : (z == 1) ? s1 : (z == 2) ? s2 : s3;
    __half* dst = (z == 0) ? d0 : (z == 1) ? d1 : (z == 2) ? d2 : d3;
    const int i = (blockIdx.x * 256 + threadIdx.x) * 8;
    float4 a = *reinterpret_cast<const float4*>(src + i);
    float4 b = *reinterpret_cast<const float4*>(src + i + 4);
    __half2 h0 = __floats2half2_rn(a.x, a.y);
    __half2 h1 = __floats2half2_rn(a.z, a.w);
    __half2 h2 = __floats2half2_rn(b.x, b.y);
    __half2 h3 = __floats2half2_rn(b.z, b.w);
    uint4 o;
    o.x = *reinterpret_cast<uint32_t*>(&h0);
    o.y = *reinterpret_cast<uint32_t*>(&h1);
    o.z = *reinterpret_cast<uint32_t*>(&h2);
    o.w = *reinterpret_cast<uint32_t*>(&h3);
    *reinterpret_cast<uint4*>(dst + i) = o;
}

// ============ mma.sync fp16 GEMM: C = A[M,K] @ W[N,K]^T + bias ==============
// CTA tile 128x256, warp tile 64x64 (8 warps = 2M x 4N), K-chunk 32.
// 4-stage cp.async pipeline, one sync per k-stage.
#define ROWB 80
#define A_BYTES (128 * ROWB)          // 10240
#define B_BYTES (256 * ROWB)          // 20480
#define STG_BYTES (A_BYTES + B_BYTES) // 30720
#define GSTAGES 4
#define GSMEM_TOTAL (GSTAGES * STG_BYTES)   // 122880

__global__ __launch_bounds__(256) void gemm_mma_kernel(
    const __half* __restrict__ A,
    const __half* __restrict__ W0,
    const __half* __restrict__ W1,
    const __half* __restrict__ W2,
    const float* __restrict__ b0p,
    const float* __restrict__ b1p,
    const float* __restrict__ b2p,
    float* __restrict__ Cf,
    __half* __restrict__ Ch0,
    __half* __restrict__ Ch1,
    __half* __restrict__ Ch2,
    int out_mode, float qscale)
{
    extern __shared__ __align__(16) char ds[];
    const int tid = threadIdx.x;
    const int wid = tid >> 5;
    const int lane = tid & 31;
    const int bm = blockIdx.y * 128;
    const int bn = blockIdx.x * 256;
    const int z = blockIdx.z;
    const int warpM = (wid & 1) * 64;
    const int warpN = (wid >> 1) * 64;

    const __half* W = (z == 0) ? W0 : (z == 1) ? W1 : W2;
    const float* bias = (z == 0) ? b0p : (z == 1) ? b1p : b2p;
    __half* Ch = (z == 0) ? Ch0 : (z == 1) ? Ch1 : Ch2;
    const float oscale = (z == 0) ? qscale : 1.0f;

    // loader: A rows 0..127 (2 threads/row), B rows 0..255 (2 rows/thread)
    const int ldRow = tid >> 1;
    const int ldH = (tid & 1) * 16;
    const __half* Ap = A + (size_t)(bm + ldRow) * 1024 + ldH;
    const __half* Wp0 = W + (size_t)(bn + ldRow) * 1024 + ldH;
    const __half* Wp1 = W + (size_t)(bn + 128 + ldRow) * 1024 + ldH;

    const uint32_t sbase = smem_u32(ds);
    const uint32_t stOffA = (uint32_t)(ldRow * ROWB + ldH * 2);
    const uint32_t stOffB0 = (uint32_t)(A_BYTES + ldRow * ROWB + ldH * 2);
    const uint32_t stOffB1 = stOffB0 + 128 * ROWB;

    float acc[4][8][4];
    #pragma unroll
    for (int mt = 0; mt < 4; mt++)
        #pragma unroll
        for (int nb = 0; nb < 8; nb++)
            #pragma unroll
            for (int r = 0; r < 4; r++) acc[mt][nb][r] = 0.0f;

    // ---- prologue: issue stages 0..2 ----
    #pragma unroll
    for (int p = 0; p < 3; p++) {
        const uint32_t sN = sbase + p * STG_BYTES;
        const int kn = p * 32;
        CP_ASYNC16(sN + stOffA, Ap + kn);
        CP_ASYNC16(sN + stOffA + 16, Ap + kn + 8);
        CP_ASYNC16(sN + stOffB0, Wp0 + kn);
        CP_ASYNC16(sN + stOffB0 + 16, Wp0 + kn + 8);
        CP_ASYNC16(sN + stOffB1, Wp1 + kn);
        CP_ASYNC16(sN + stOffB1 + 16, Wp1 + kn + 8);
        CP_COMMIT();
    }

    // ldmatrix address components
    const int lr = lane & 7;
    const int aRow = warpM + lr + ((lane >> 3) & 1) * 8;
    const int aKb  = ((lane >> 4) & 1) * 16;
    const int bRow = warpN + lr + ((lane >> 4) & 1) * 8;
    const int bKb  = ((lane >> 3) & 1) * 16;

    for (int s = 0; s < 32; s++) {
        if (s < 30) { CP_WAIT2(); }
        else if (s == 30) { CP_WAIT1(); }
        else { CP_WAIT0(); }
        __syncthreads();

        if (s + 3 < 32) {
            const uint32_t sN = sbase + ((s + 3) & 3) * STG_BYTES;
            const int kn = (s + 3) * 32;
            CP_ASYNC16(sN + stOffA, Ap + kn);
            CP_ASYNC16(sN + stOffA + 16, Ap + kn + 8);
            CP_ASYNC16(sN + stOffB0, Wp0 + kn);
            CP_ASYNC16(sN + stOffB0 + 16, Wp0 + kn + 8);
            CP_ASYNC16(sN + stOffB1, Wp1 + kn);
            CP_ASYNC16(sN + stOffB1 + 16, Wp1 + kn + 8);
            CP_COMMIT();
        }

        // ---- compute stage s ----
        const uint32_t sA = sbase + (s & 3) * STG_BYTES;
        const uint32_t sB = sA + A_BYTES;
        #pragma unroll
        for (int kt = 0; kt < 2; kt++) {
            uint32_t af[4][4];
            #pragma unroll
            for (int mt = 0; mt < 4; mt++)
                LDSM_X4(af[mt], sA + (uint32_t)((aRow + mt * 16) * ROWB + kt * 32 + aKb));
            uint32_t bf[4][4];
            #pragma unroll
            for (int nb2 = 0; nb2 < 4; nb2++)
                LDSM_X4(bf[nb2], sB + (uint32_t)((bRow + nb2 * 16) * ROWB + kt * 32 + bKb));
            #pragma unroll
            for (int mt = 0; mt < 4; mt++) {
                #pragma unroll
                for (int nb2 = 0; nb2 < 4; nb2++) {
                    mma16816h(acc[mt][2 * nb2 + 0], af[mt], bf[nb2][0], bf[nb2][1]);
                    mma16816h(acc[mt][2 * nb2 + 1], af[mt], bf[nb2][2], bf[nb2][3]);
                }
            }
        }
    }

    // ---- epilogue ----
    const int gRow = lane >> 2;
    const int gCol = (lane & 3) * 2;
    #pragma unroll
    for (int mt = 0; mt < 4; mt++) {
        #pragma unroll
        for (int half_ = 0; half_ < 2; half_++) {
            const int m = bm + warpM + mt * 16 + gRow + half_ * 8;
            const int b = m >> 11;
            const int srow = m & 2047;
            #pragma unroll
            for (int nb = 0; nb < 8; nb++) {
                const int n = bn + warpN + nb * 8 + gCol;
                float vx = acc[mt][nb][half_ * 2 + 0] + bias[n];
                float vy = acc[mt][nb][half_ * 2 + 1] + bias[n + 1];
                if (out_mode == 1) {
                    const int h = n >> 6;
                    const int d = n & 63;
                    __half2 hv = __floats2half2_rn(vx * oscale, vy * oscale);
                    *reinterpret_cast<__half2*>(
                        Ch + (((size_t)(b * HH + h) << 11) + srow) * DD + d) = hv;
                } else {
                    *reinterpret_cast<float2*>(Cf + (size_t)m * EE + n) =
                        make_float2(vx, vy);
                }
            }
        }
    }
}

// ============ Flash attention via mma.sync fp16 (unchanged) =================
#define FROWB 144                       // 64 halves (128B) + 16B pad
#define QS_BYTES (128 * FROWB)          // 18432
#define KV_HALF (64 * FROWB)            // 9216
#define KV_STG (2 * KV_HALF)            // 18432 per stage (K + V)
#define FSMEM  (QS_BYTES + 2 * KV_STG)  // 55296

__global__ __launch_bounds__(256) void flash_mma_kernel(
    const __half* __restrict__ Q,
    const __half* __restrict__ K,
    const __half* __restrict__ V,
    __half* __restrict__ ctx)           // [b,s,e] fp16
{
    __shared__ __align__(16) char sm[FSMEM];
    const int bh = blockIdx.y;
    const int q0 = blockIdx.x * 128;
    const int tid = threadIdx.x;
    const int wid = tid >> 5;
    const int lane = tid & 31;
    const int warpM = wid * 16;
    const uint32_t sb = smem_u32(sm);

    const __half* Qbh = Q + (size_t)bh * SS * DD;
    const __half* Kbh = K + (size_t)bh * SS * DD;
    const __half* Vbh = V + (size_t)bh * SS * DD;

    const int lrow = tid >> 2;
    const int lcb = (tid & 3) * 32;
    const uint32_t kvb0 = sb + QS_BYTES;
    const uint32_t kvb1 = sb + QS_BYTES + KV_STG;

    {
        const int r = tid >> 1;
        const int ch = (tid & 1) * 32;
        const uint4* src = reinterpret_cast<const uint4*>(Qbh + (size_t)(q0 + r) * DD + ch);
        char* dst = sm + r * FROWB + ch * 2;
        reinterpret_cast<uint4*>(dst)[0] = src[0];
        reinterpret_cast<uint4*>(dst)[1] = src[1];
        reinterpret_cast<uint4*>(dst)[2] = src[2];
        reinterpret_cast<uint4*>(dst)[3] = src[3];
    }

    {
        const uint32_t kd = kvb0 + (uint32_t)(lrow * FROWB + lcb);
        const char* kg = reinterpret_cast<const char*>(Kbh + (size_t)lrow * DD) + lcb;
        CP_ASYNC16(kd, kg);
        CP_ASYNC16(kd + 16, kg + 16);
        const uint32_t vd = kd + KV_HALF;
        const char* vg = reinterpret_cast<const char*>(Vbh + (size_t)lrow * DD) + lcb;
        CP_ASYNC16(vd, vg);
        CP_ASYNC16(vd + 16, vg + 16);
        CP_COMMIT();
    }
    CP_WAIT0();
    __syncthreads();

    const int lr = lane & 7;
    const int aRow = warpM + lr + ((lane >> 3) & 1) * 8;
    const int aCb  = ((lane >> 4) & 1) * 16;
    uint32_t qf[4][4];
    #pragma unroll
    for (int ks = 0; ks < 4; ks++)
        LDSM_X4(qf[ks], sb + (uint32_t)(aRow * FROWB + ks * 32 + aCb));

    float m0 = -1e30f, m1 = -1e30f;
    float lacc[4];
    lacc[0] = lacc[1] = lacc[2] = lacc[3] = 0.0f;
    float o[8][4];
    #pragma unroll
    for (int d8 = 0; d8 < 8; d8++)
        #pragma unroll
        for (int r = 0; r < 4; r++) o[d8][r] = 0.0f;

    const int bRowK = lr + ((lane >> 4) & 1) * 8;
    const int bCbK  = ((lane >> 3) & 1) * 16;
    const int vRowB = lr + ((lane >> 3) & 1) * 8;
    const int vCbB  = ((lane >> 4) & 1) * 16;
    const uint32_t ONES = 0x3C003C00u;

    for (int kt = 0; kt < 32; kt++) {
        const uint32_t kvb = (kt & 1) ? kvb1 : kvb0;

        if (kt < 31) {
            const int krow = (kt + 1) * 64 + lrow;
            const uint32_t nb = ((kt + 1) & 1) ? kvb1 : kvb0;
            const uint32_t kd = nb + (uint32_t)(lrow * FROWB + lcb);
            const char* kg = reinterpret_cast<const char*>(Kbh + (size_t)krow * DD) + lcb;
            CP_ASYNC16(kd, kg);
            CP_ASYNC16(kd + 16, kg + 16);
            const uint32_t vd = kd + KV_HALF;
            const char* vg = reinterpret_cast<const char*>(Vbh + (size_t)krow * DD) + lcb;
            CP_ASYNC16(vd, vg);
            CP_ASYNC16(vd + 16, vg + 16);
            CP_COMMIT();
        }

        float sc[8][4];
        #pragma unroll
        for (int nb = 0; nb < 8; nb++)
            #pragma unroll
            for (int r = 0; r < 4; r++) sc[nb][r] = 0.0f;
        #pragma unroll
        for (int ks = 0; ks < 4; ks++) {
            #pragma unroll
            for (int ng2 = 0; ng2 < 4; ng2++) {
                uint32_t kf[4];
                LDSM_X4(kf, kvb + (uint32_t)((ng2 * 16 + bRowK) * FROWB + ks * 32 + bCbK));
                mma16816h(sc[2 * ng2 + 0], qf[ks], kf[0], kf[1]);
                mma16816h(sc[2 * ng2 + 1], qf[ks], kf[2], kf[3]);
            }
        }

        float mx0 = sc[0][0], mx1 = sc[0][2];
        #pragma unroll
        for (int nb = 0; nb < 8; nb++) {
            mx0 = fmaxf(mx0, fmaxf(sc[nb][0], sc[nb][1]));
            mx1 = fmaxf(mx1, fmaxf(sc[nb][2], sc[nb][3]));
        }
        mx0 = fmaxf(mx0, __shfl_xor_sync(0xffffffffu, mx0, 1));
        mx0 = fmaxf(mx0, __shfl_xor_sync(0xffffffffu, mx0, 2));
        mx1 = fmaxf(mx1, __shfl_xor_sync(0xffffffffu, mx1, 1));
        mx1 = fmaxf(mx1, __shfl_xor_sync(0xffffffffu, mx1, 2));
        const float mn0 = fmaxf(m0, mx0);
        const float mn1 = fmaxf(m1, mx1);
        const float c0 = exp2f(m0 - mn0);
        const float c1 = exp2f(m1 - mn1);
        m0 = mn0; m1 = mn1;

        uint32_t pa0[8], pa1[8];
        #pragma unroll
        for (int nb = 0; nb < 8; nb++) {
            __half2 h0 = __floats2half2_rn(sc[nb][0] - mn0, sc[nb][1] - mn0);
            __half2 h1 = __floats2half2_rn(sc[nb][2] - mn1, sc[nb][3] - mn1);
            pa0[nb] = ex2_h2(*reinterpret_cast<uint32_t*>(&h0));
            pa1[nb] = ex2_h2(*reinterpret_cast<uint32_t*>(&h1));
        }

        lacc[0] *= c0; lacc[2] *= c1;
        #pragma unroll
        for (int d8 = 0; d8 < 8; d8++) {
            o[d8][0] *= c0; o[d8][1] *= c0;
            o[d8][2] *= c1; o[d8][3] *= c1;
        }

        const uint32_t vbase = kvb + KV_HALF;
        #pragma unroll
        for (int ks = 0; ks < 4; ks++) {
            uint32_t pf[4] = {pa0[2 * ks], pa1[2 * ks], pa0[2 * ks + 1], pa1[2 * ks + 1]};
            mma16816h(lacc, pf, ONES, ONES);
            #pragma unroll
            for (int dg2 = 0; dg2 < 4; dg2++) {
                uint32_t vf[4];
                LDSM_T_X4(vf, vbase + (uint32_t)((ks * 16 + vRowB) * FROWB + dg2 * 32 + vCbB));
                mma16816h(o[2 * dg2 + 0], pf, vf[0], vf[1]);
                mma16816h(o[2 * dg2 + 1], pf, vf[2], vf[3]);
            }
        }

        if (kt < 31) {
            CP_WAIT0();
            __syncthreads();
        }
    }

    const float i0 = 1.0f / lacc[0];
    const float i1 = 1.0f / lacc[2];

    const int b = bh >> 4;
    const int h = bh & 15;
    const int g = lane >> 2;
    const int t2 = (lane & 3) * 2;
    const int r0 = q0 + warpM + g;
    __half* d0 = ctx + ((size_t)(b * SS + r0)) * EE + h * DD;
    __half* d1 = ctx + ((size_t)(b * SS + r0 + 8)) * EE + h * DD;
    #pragma unroll
    for (int d8 = 0; d8 < 8; d8++) {
        *reinterpret_cast<__half2*>(d0 + d8 * 8 + t2) =
            __floats2half2_rn(o[d8][0] * i0, o[d8][1] * i0);
        *reinterpret_cast<__half2*>(d1 + d8 * 8 + t2) =
            __floats2half2_rn(o[d8][2] * i1, o[d8][3] * i1);
    }
}

// ---------------- launch ----------------------------------------------------
extern "C" void kernel_launch(void* const* d_in, const int* in_sizes, int n_in,
                              void* d_out, int out_size)
{
    const float* x  = (const float*)d_in[0];
    const float* Wq = (const float*)d_in[1];
    const float* bq = (const float*)d_in[2];
    const float* Wk = (const float*)d_in[3];
    const float* bk = (const float*)d_in[4];
    const float* Wv = (const float*)d_in[5];
    const float* bv = (const float*)d_in[6];
    const float* Wo = (const float*)d_in[7];
    const float* bo = (const float*)d_in[8];
    float* out = (float*)d_out;

    __half *xh, *Wqh, *Wkh, *Wvh, *Woh, *Qp, *Kp, *Vp, *Cp;
    cudaGetSymbolAddress((void**)&xh,  g_xh);
    cudaGetSymbolAddress((void**)&Wqh, g_Wqh);
    cudaGetSymbolAddress((void**)&Wkh, g_Wkh);
    cudaGetSymbolAddress((void**)&Wvh, g_Wvh);
    cudaGetSymbolAddress((void**)&Woh, g_Woh);
    cudaGetSymbolAddress((void**)&Qp,  g_Qh);
    cudaGetSymbolAddress((void**)&Kp,  g_Kh);
    cudaGetSymbolAddress((void**)&Vp,  g_Vh);
    cudaGetSymbolAddress((void**)&Cp,  g_ctxh);

    cudaFuncSetAttribute(gemm_mma_kernel,
                         cudaFuncAttributeMaxDynamicSharedMemorySize, GSMEM_TOTAL);

    // ---- convert inputs to fp16 (x + 4 weights in 2 launches) ----
    const int NW = EE * EE;          // 1M
    const int NX = MM * EE;          // 4M
    cvt_f2h_kernel<<<NX / (256 * 8), 256>>>(x, xh, NX);
    dim3 wGrid(NW / (256 * 8), 4);
    cvt_w_kernel<<<wGrid, 256>>>(Wq, Wk, Wv, Wo, Wqh, Wkh, Wvh, Woh);

    // Q pre-scaled by 0.125 * log2(e) so softmax uses exp2 directly
    const float qscale = 0.18033688011112042f;

    // ---- merged Q/K/V projections (z selects target) ----
    dim3 qkvGrid(EE / 256, MM / 128, 3);   // (4, 32, 3) = 384 CTAs
    gemm_mma_kernel<<<qkvGrid, 256, GSMEM_TOTAL>>>(
        xh, Wqh, Wkh, Wvh, bq, bk, bv, nullptr, Qp, Kp, Vp, 1, qscale);

    // ---- attention ----
    dim3 faGrid(SS / 128, BB * HH);        // (16, 32)
    flash_mma_kernel<<<faGrid, dim3(256)>>>(Qp, Kp, Vp, Cp);

    // ---- output projection ----
    dim3 oGrid(EE / 256, MM / 128, 1);     // 128 CTAs
    gemm_mma_kernel<<<oGrid, 256, GSMEM_TOTAL>>>(
        Cp, Woh, Woh, Woh, bo, bo, bo, out, nullptr, nullptr, nullptr, 0, 1.0f);
}

// round 17
// speedup vs baseline: 1.4165x; 1.4165x over previous
#include <cuda_runtime.h>
#include <cuda_bf16.h>
#include <cuda_fp16.h>
#include <cstdint>

// Problem constants
#define BB 2
#define SS 2048
#define EE 1024
#define HH 16
#define DD 64
#define MM (BB * SS)   // 4096

// ---------------- scratch (device globals; no allocation allowed) ----------
__device__ __half g_xh[MM * EE];             // fp16 copy of x [4096,1024]
__device__ __half g_Wqh[EE * EE];
__device__ __half g_Wkh[EE * EE];
__device__ __half g_Wvh[EE * EE];
__device__ __half g_Woh[EE * EE];
__device__ __half g_Qh[BB * HH * SS * DD];   // [b,h,s,d] fp16 (pre-scaled)
__device__ __half g_Kh[BB * HH * SS * DD];
__device__ __half g_Vh[BB * HH * SS * DD];
__device__ __half g_ctxh[BB * SS * EE];      // [b,s,e] fp16

// ======================= helpers ===========================================
__device__ __forceinline__ uint32_t smem_u32(const void* p) {
    uint32_t a;
    asm("{ .reg .u64 t; cvta.to.shared.u64 t, %1; cvt.u32.u64 %0, t; }" : "=r"(a) : "l"(p));
    return a;
}

#define CP_ASYNC16(saddr, gptr) \
    asm volatile("cp.async.cg.shared.global [%0], [%1], 16;" \
                 :: "r"(saddr), "l"(gptr) : "memory")
#define CP_COMMIT() asm volatile("cp.async.commit_group;" ::: "memory")
#define CP_WAIT0()  asm volatile("cp.async.wait_group 0;" ::: "memory")
#define CP_WAIT1()  asm volatile("cp.async.wait_group 1;" ::: "memory")

#define LDSM_X4(r, addr) \
    asm volatile("ldmatrix.sync.aligned.m8n8.x4.shared.b16 {%0,%1,%2,%3}, [%4];" \
        : "=r"((r)[0]), "=r"((r)[1]), "=r"((r)[2]), "=r"((r)[3]) : "r"(addr))

#define LDSM_T_X4(r, addr) \
    asm volatile("ldmatrix.sync.aligned.m8n8.x4.trans.shared.b16 {%0,%1,%2,%3}, [%4];" \
        : "=r"((r)[0]), "=r"((r)[1]), "=r"((r)[2]), "=r"((r)[3]) : "r"(addr))

__device__ __forceinline__ void mma16816h(float* c, const uint32_t* a,
                                          uint32_t b0, uint32_t b1) {
    asm volatile(
        "mma.sync.aligned.m16n8k16.row.col.f32.f16.f16.f32 "
        "{%0,%1,%2,%3}, {%4,%5,%6,%7}, {%8,%9}, {%0,%1,%2,%3};"
        : "+f"(c[0]), "+f"(c[1]), "+f"(c[2]), "+f"(c[3])
        : "r"(a[0]), "r"(a[1]), "r"(a[2]), "r"(a[3]), "r"(b0), "r"(b1));
}

__device__ __forceinline__ uint32_t ex2_h2(uint32_t u) {
    asm("ex2.approx.f16x2 %0, %1;" : "=r"(u) : "r"(u));
    return u;
}

// ================ fp32 -> fp16 convert passes ===============================
__global__ __launch_bounds__(256) void cvt_f2h_kernel(
    const float* __restrict__ src, __half* __restrict__ dst, int n)
{
    const int i = (blockIdx.x * 256 + threadIdx.x) * 8;
    if (i >= n) return;
    float4 a = *reinterpret_cast<const float4*>(src + i);
    float4 b = *reinterpret_cast<const float4*>(src + i + 4);
    __half2 h0 = __floats2half2_rn(a.x, a.y);
    __half2 h1 = __floats2half2_rn(a.z, a.w);
    __half2 h2 = __floats2half2_rn(b.x, b.y);
    __half2 h3 = __floats2half2_rn(b.z, b.w);
    uint4 o;
    o.x = *reinterpret_cast<uint32_t*>(&h0);
    o.y = *reinterpret_cast<uint32_t*>(&h1);
    o.z = *reinterpret_cast<uint32_t*>(&h2);
    o.w = *reinterpret_cast<uint32_t*>(&h3);
    *reinterpret_cast<uint4*>(dst + i) = o;
}

__global__ __launch_bounds__(256) void cvt_w_kernel(
    const float* __restrict__ s0, const float* __restrict__ s1,
    const float* __restrict__ s2, const float* __restrict__ s3,
    __half* __restrict__ d0, __half* __restrict__ d1,
    __half* __restrict__ d2, __half* __restrict__ d3)
{
    const int z = blockIdx.y;
    const float* src = (z == 0) ? s0 : (z == 1) ? s1 : (z == 2) ? s2 : s3;
    __half* dst = (z == 0) ? d0 : (z == 1) ? d1 : (z == 2) ? d2 : d3;
    const int i = (blockIdx.x * 256 + threadIdx.x) * 8;
    float4 a = *reinterpret_cast<const float4*>(src + i);
    float4 b = *reinterpret_cast<const float4*>(src + i + 4);
    __half2 h0 = __floats2half2_rn(a.x, a.y);
    __half2 h1 = __floats2half2_rn(a.z, a.w);
    __half2 h2 = __floats2half2_rn(b.x, b.y);
    __half2 h3 = __floats2half2_rn(b.z, b.w);
    uint4 o;
    o.x = *reinterpret_cast<uint32_t*>(&h0);
    o.y = *reinterpret_cast<uint32_t*>(&h1);
    o.z = *reinterpret_cast<uint32_t*>(&h2);
    o.w = *reinterpret_cast<uint32_t*>(&h3);
    *reinterpret_cast<uint4*>(dst + i) = o;
}

// ============ mma.sync fp16 GEMM: C = A[M,K] @ W[N,K]^T + bias ==============
// CTA tile 128x128, warp tile 32x64 (8 warps 4x2), K-chunk 64 per stage,
// 3-stage cp.async pipeline (2 CTAs/SM). 16 syncs; 64 MMA/warp per sync.
#define GROWB 144                      // 64 halves (128B) + 16B pad
#define GA_BYTES (128 * GROWB)         // 18432
#define GSTG (2 * GA_BYTES)            // 36864: A + B
#define GSTAGES 3
#define GSMEM_TOTAL (GSTAGES * GSTG)   // 110592

__global__ __launch_bounds__(256) void gemm_mma_kernel(
    const __half* __restrict__ A,
    const __half* __restrict__ W0,
    const __half* __restrict__ W1,
    const __half* __restrict__ W2,
    const float* __restrict__ b0p,
    const float* __restrict__ b1p,
    const float* __restrict__ b2p,
    float* __restrict__ Cf,
    __half* __restrict__ Ch0,
    __half* __restrict__ Ch1,
    __half* __restrict__ Ch2,
    int out_mode, float qscale)
{
    extern __shared__ __align__(16) char ds[];
    const int tid = threadIdx.x;
    const int wid = tid >> 5;
    const int lane = tid & 31;
    const int bm = blockIdx.y * 128;
    const int bn = blockIdx.x * 128;
    const int z = blockIdx.z;
    const int warpM = (wid & 3) * 32;
    const int warpN = (wid >> 2) * 64;

    const __half* W = (z == 0) ? W0 : (z == 1) ? W1 : W2;
    const float* bias = (z == 0) ? b0p : (z == 1) ? b1p : b2p;
    __half* Ch = (z == 0) ? Ch0 : (z == 1) ? Ch1 : Ch2;
    const float oscale = (z == 0) ? qscale : 1.0f;

    // loader: 2 threads per row, 32 consecutive k-halves (64B) per thread
    const int ldRow = tid >> 1;
    const int ldH = (tid & 1) * 32;   // halves
    const __half* Ap = A + (size_t)(bm + ldRow) * 1024 + ldH;
    const __half* Wp = W + (size_t)(bn + ldRow) * 1024 + ldH;

    const uint32_t sbase = smem_u32(ds);
    const uint32_t stOffA = (uint32_t)(ldRow * GROWB + ldH * 2);
    const uint32_t stOffB = stOffA + GA_BYTES;

    float acc[2][8][4];
    #pragma unroll
    for (int mt = 0; mt < 2; mt++)
        #pragma unroll
        for (int nb = 0; nb < 8; nb++)
            #pragma unroll
            for (int r = 0; r < 4; r++) acc[mt][nb][r] = 0.0f;

    // ---- prologue: issue stages 0,1 ----
    #pragma unroll
    for (int p = 0; p < 2; p++) {
        const uint32_t sN = sbase + p * GSTG;
        const int kn = p * 64;
        CP_ASYNC16(sN + stOffA, Ap + kn);
        CP_ASYNC16(sN + stOffA + 16, Ap + kn + 8);
        CP_ASYNC16(sN + stOffA + 32, Ap + kn + 16);
        CP_ASYNC16(sN + stOffA + 48, Ap + kn + 24);
        CP_ASYNC16(sN + stOffB, Wp + kn);
        CP_ASYNC16(sN + stOffB + 16, Wp + kn + 8);
        CP_ASYNC16(sN + stOffB + 32, Wp + kn + 16);
        CP_ASYNC16(sN + stOffB + 48, Wp + kn + 24);
        CP_COMMIT();
    }

    // ldmatrix address components
    const int lr = lane & 7;
    const int aRow = warpM + lr + ((lane >> 3) & 1) * 8;
    const int aKb  = ((lane >> 4) & 1) * 16;
    const int bRow = warpN + lr + ((lane >> 4) & 1) * 8;
    const int bKb  = ((lane >> 3) & 1) * 16;

    // stage index buffers cycle mod 3
    int bufc = 0;   // buffer of stage s
    for (int s = 0; s < 16; s++) {
        if (s < 15) { CP_WAIT1(); } else { CP_WAIT0(); }
        __syncthreads();

        // issue stage s+2 into buffer (bufc+2)%3 (= buffer of s-1, safe)
        if (s + 2 < 16) {
            int nb3 = bufc + 2; if (nb3 >= 3) nb3 -= 3;
            const uint32_t sN = sbase + nb3 * GSTG;
            const int kn = (s + 2) * 64;
            CP_ASYNC16(sN + stOffA, Ap + kn);
            CP_ASYNC16(sN + stOffA + 16, Ap + kn + 8);
            CP_ASYNC16(sN + stOffA + 32, Ap + kn + 16);
            CP_ASYNC16(sN + stOffA + 48, Ap + kn + 24);
            CP_ASYNC16(sN + stOffB, Wp + kn);
            CP_ASYNC16(sN + stOffB + 16, Wp + kn + 8);
            CP_ASYNC16(sN + stOffB + 32, Wp + kn + 16);
            CP_ASYNC16(sN + stOffB + 48, Wp + kn + 24);
            CP_COMMIT();
        }

        // ---- compute stage s (K=64: 4 kt groups) ----
        const uint32_t sA = sbase + bufc * GSTG;
        const uint32_t sB = sA + GA_BYTES;
        #pragma unroll
        for (int kt = 0; kt < 4; kt++) {
            uint32_t af[2][4];
            #pragma unroll
            for (int mt = 0; mt < 2; mt++)
                LDSM_X4(af[mt], sA + (uint32_t)((aRow + mt * 16) * GROWB + kt * 32 + aKb));
            uint32_t bf[4][4];
            #pragma unroll
            for (int nb2 = 0; nb2 < 4; nb2++)
                LDSM_X4(bf[nb2], sB + (uint32_t)((bRow + nb2 * 16) * GROWB + kt * 32 + bKb));
            #pragma unroll
            for (int mt = 0; mt < 2; mt++) {
                #pragma unroll
                for (int nb2 = 0; nb2 < 4; nb2++) {
                    mma16816h(acc[mt][2 * nb2 + 0], af[mt], bf[nb2][0], bf[nb2][1]);
                    mma16816h(acc[mt][2 * nb2 + 1], af[mt], bf[nb2][2], bf[nb2][3]);
                }
            }
        }

        if (++bufc >= 3) bufc = 0;
    }

    // ---- epilogue ----
    const int gRow = lane >> 2;
    const int gCol = (lane & 3) * 2;
    #pragma unroll
    for (int mt = 0; mt < 2; mt++) {
        #pragma unroll
        for (int half_ = 0; half_ < 2; half_++) {
            const int m = bm + warpM + mt * 16 + gRow + half_ * 8;
            const int b = m >> 11;
            const int srow = m & 2047;
            #pragma unroll
            for (int nb = 0; nb < 8; nb++) {
                const int n = bn + warpN + nb * 8 + gCol;
                float vx = acc[mt][nb][half_ * 2 + 0] + bias[n];
                float vy = acc[mt][nb][half_ * 2 + 1] + bias[n + 1];
                if (out_mode == 1) {
                    const int h = n >> 6;
                    const int d = n & 63;
                    __half2 hv = __floats2half2_rn(vx * oscale, vy * oscale);
                    *reinterpret_cast<__half2*>(
                        Ch + (((size_t)(b * HH + h) << 11) + srow) * DD + d) = hv;
                } else {
                    *reinterpret_cast<float2*>(Cf + (size_t)m * EE + n) =
                        make_float2(vx, vy);
                }
            }
        }
    }
}

// ============ Flash attention via mma.sync fp16 (R15, unchanged) ============
#define FROWB 144                       // 64 halves (128B) + 16B pad
#define QS_BYTES (128 * FROWB)          // 18432
#define KV_HALF (64 * FROWB)            // 9216
#define KV_STG (2 * KV_HALF)            // 18432 per stage (K + V)
#define FSMEM  (QS_BYTES + 2 * KV_STG)  // 55296

__global__ __launch_bounds__(256) void flash_mma_kernel(
    const __half* __restrict__ Q,
    const __half* __restrict__ K,
    const __half* __restrict__ V,
    __half* __restrict__ ctx)           // [b,s,e] fp16
{
    __shared__ __align__(16) char sm[FSMEM];
    const int bh = blockIdx.y;
    const int q0 = blockIdx.x * 128;
    const int tid = threadIdx.x;
    const int wid = tid >> 5;
    const int lane = tid & 31;
    const int warpM = wid * 16;
    const uint32_t sb = smem_u32(sm);

    const __half* Qbh = Q + (size_t)bh * SS * DD;
    const __half* Kbh = K + (size_t)bh * SS * DD;
    const __half* Vbh = V + (size_t)bh * SS * DD;

    const int lrow = tid >> 2;
    const int lcb = (tid & 3) * 32;
    const uint32_t kvb0 = sb + QS_BYTES;
    const uint32_t kvb1 = sb + QS_BYTES + KV_STG;

    {
        const int r = tid >> 1;
        const int ch = (tid & 1) * 32;
        const uint4* src = reinterpret_cast<const uint4*>(Qbh + (size_t)(q0 + r) * DD + ch);
        char* dst = sm + r * FROWB + ch * 2;
        reinterpret_cast<uint4*>(dst)[0] = src[0];
        reinterpret_cast<uint4*>(dst)[1] = src[1];
        reinterpret_cast<uint4*>(dst)[2] = src[2];
        reinterpret_cast<uint4*>(dst)[3] = src[3];
    }

    {
        const uint32_t kd = kvb0 + (uint32_t)(lrow * FROWB + lcb);
        const char* kg = reinterpret_cast<const char*>(Kbh + (size_t)lrow * DD) + lcb;
        CP_ASYNC16(kd, kg);
        CP_ASYNC16(kd + 16, kg + 16);
        const uint32_t vd = kd + KV_HALF;
        const char* vg = reinterpret_cast<const char*>(Vbh + (size_t)lrow * DD) + lcb;
        CP_ASYNC16(vd, vg);
        CP_ASYNC16(vd + 16, vg + 16);
        CP_COMMIT();
    }
    CP_WAIT0();
    __syncthreads();

    const int lr = lane & 7;
    const int aRow = warpM + lr + ((lane >> 3) & 1) * 8;
    const int aCb  = ((lane >> 4) & 1) * 16;
    uint32_t qf[4][4];
    #pragma unroll
    for (int ks = 0; ks < 4; ks++)
        LDSM_X4(qf[ks], sb + (uint32_t)(aRow * FROWB + ks * 32 + aCb));

    float m0 = -1e30f, m1 = -1e30f;
    float lacc[4];
    lacc[0] = lacc[1] = lacc[2] = lacc[3] = 0.0f;
    float o[8][4];
    #pragma unroll
    for (int d8 = 0; d8 < 8; d8++)
        #pragma unroll
        for (int r = 0; r < 4; r++) o[d8][r] = 0.0f;

    const int bRowK = lr + ((lane >> 4) & 1) * 8;
    const int bCbK  = ((lane >> 3) & 1) * 16;
    const int vRowB = lr + ((lane >> 3) & 1) * 8;
    const int vCbB  = ((lane >> 4) & 1) * 16;
    const uint32_t ONES = 0x3C003C00u;

    for (int kt = 0; kt < 32; kt++) {
        const uint32_t kvb = (kt & 1) ? kvb1 : kvb0;

        if (kt < 31) {
            const int krow = (kt + 1) * 64 + lrow;
            const uint32_t nb = ((kt + 1) & 1) ? kvb1 : kvb0;
            const uint32_t kd = nb + (uint32_t)(lrow * FROWB + lcb);
            const char* kg = reinterpret_cast<const char*>(Kbh + (size_t)krow * DD) + lcb;
            CP_ASYNC16(kd, kg);
            CP_ASYNC16(kd + 16, kg + 16);
            const uint32_t vd = kd + KV_HALF;
            const char* vg = reinterpret_cast<const char*>(Vbh + (size_t)krow * DD) + lcb;
            CP_ASYNC16(vd, vg);
            CP_ASYNC16(vd + 16, vg + 16);
            CP_COMMIT();
        }

        float sc[8][4];
        #pragma unroll
        for (int nb = 0; nb < 8; nb++)
            #pragma unroll
            for (int r = 0; r < 4; r++) sc[nb][r] = 0.0f;
        #pragma unroll
        for (int ks = 0; ks < 4; ks++) {
            #pragma unroll
            for (int ng2 = 0; ng2 < 4; ng2++) {
                uint32_t kf[4];
                LDSM_X4(kf, kvb + (uint32_t)((ng2 * 16 + bRowK) * FROWB + ks * 32 + bCbK));
                mma16816h(sc[2 * ng2 + 0], qf[ks], kf[0], kf[1]);
                mma16816h(sc[2 * ng2 + 1], qf[ks], kf[2], kf[3]);
            }
        }

        float mx0 = sc[0][0], mx1 = sc[0][2];
        #pragma unroll
        for (int nb = 0; nb < 8; nb++) {
            mx0 = fmaxf(mx0, fmaxf(sc[nb][0], sc[nb][1]));
            mx1 = fmaxf(mx1, fmaxf(sc[nb][2], sc[nb][3]));
        }
        mx0 = fmaxf(mx0, __shfl_xor_sync(0xffffffffu, mx0, 1));
        mx0 = fmaxf(mx0, __shfl_xor_sync(0xffffffffu, mx0, 2));
        mx1 = fmaxf(mx1, __shfl_xor_sync(0xffffffffu, mx1, 1));
        mx1 = fmaxf(mx1, __shfl_xor_sync(0xffffffffu, mx1, 2));
        const float mn0 = fmaxf(m0, mx0);
        const float mn1 = fmaxf(m1, mx1);
        const float c0 = exp2f(m0 - mn0);
        const float c1 = exp2f(m1 - mn1);
        m0 = mn0; m1 = mn1;

        uint32_t pa0[8], pa1[8];
        #pragma unroll
        for (int nb = 0; nb < 8; nb++) {
            __half2 h0 = __floats2half2_rn(sc[nb][0] - mn0, sc[nb][1] - mn0);
            __half2 h1 = __floats2half2_rn(sc[nb][2] - mn1, sc[nb][3] - mn1);
            pa0[nb] = ex2_h2(*reinterpret_cast<uint32_t*>(&h0));
            pa1[nb] = ex2_h2(*reinterpret_cast<uint32_t*>(&h1));
        }

        lacc[0] *= c0; lacc[2] *= c1;
        #pragma unroll
        for (int d8 = 0; d8 < 8; d8++) {
            o[d8][0] *= c0; o[d8][1] *= c0;
            o[d8][2] *= c1; o[d8][3] *= c1;
        }

        const uint32_t vbase = kvb + KV_HALF;
        #pragma unroll
        for (int ks = 0; ks < 4; ks++) {
            uint32_t pf[4] = {pa0[2 * ks], pa1[2 * ks], pa0[2 * ks + 1], pa1[2 * ks + 1]};
            mma16816h(lacc, pf, ONES, ONES);
            #pragma unroll
            for (int dg2 = 0; dg2 < 4; dg2++) {
                uint32_t vf[4];
                LDSM_T_X4(vf, vbase + (uint32_t)((ks * 16 + vRowB) * FROWB + dg2 * 32 + vCbB));
                mma16816h(o[2 * dg2 + 0], pf, vf[0], vf[1]);
                mma16816h(o[2 * dg2 + 1], pf, vf[2], vf[3]);
            }
        }

        if (kt < 31) {
            CP_WAIT0();
            __syncthreads();
        }
    }

    const float i0 = 1.0f / lacc[0];
    const float i1 = 1.0f / lacc[2];

    const int b = bh >> 4;
    const int h = bh & 15;
    const int g = lane >> 2;
    const int t2 = (lane & 3) * 2;
    const int r0 = q0 + warpM + g;
    __half* d0 = ctx + ((size_t)(b * SS + r0)) * EE + h * DD;
    __half* d1 = ctx + ((size_t)(b * SS + r0 + 8)) * EE + h * DD;
    #pragma unroll
    for (int d8 = 0; d8 < 8; d8++) {
        *reinterpret_cast<__half2*>(d0 + d8 * 8 + t2) =
            __floats2half2_rn(o[d8][0] * i0, o[d8][1] * i0);
        *reinterpret_cast<__half2*>(d1 + d8 * 8 + t2) =
            __floats2half2_rn(o[d8][2] * i1, o[d8][3] * i1);
    }
}

// ---------------- launch ----------------------------------------------------
extern "C" void kernel_launch(void* const* d_in, const int* in_sizes, int n_in,
                              void* d_out, int out_size)
{
    const float* x  = (const float*)d_in[0];
    const float* Wq = (const float*)d_in[1];
    const float* bq = (const float*)d_in[2];
    const float* Wk = (const float*)d_in[3];
    const float* bk = (const float*)d_in[4];
    const float* Wv = (const float*)d_in[5];
    const float* bv = (const float*)d_in[6];
    const float* Wo = (const float*)d_in[7];
    const float* bo = (const float*)d_in[8];
    float* out = (float*)d_out;

    __half *xh, *Wqh, *Wkh, *Wvh, *Woh, *Qp, *Kp, *Vp, *Cp;
    cudaGetSymbolAddress((void**)&xh,  g_xh);
    cudaGetSymbolAddress((void**)&Wqh, g_Wqh);
    cudaGetSymbolAddress((void**)&Wkh, g_Wkh);
    cudaGetSymbolAddress((void**)&Wvh, g_Wvh);
    cudaGetSymbolAddress((void**)&Woh, g_Woh);
    cudaGetSymbolAddress((void**)&Qp,  g_Qh);
    cudaGetSymbolAddress((void**)&Kp,  g_Kh);
    cudaGetSymbolAddress((void**)&Vp,  g_Vh);
    cudaGetSymbolAddress((void**)&Cp,  g_ctxh);

    cudaFuncSetAttribute(gemm_mma_kernel,
                         cudaFuncAttributeMaxDynamicSharedMemorySize, GSMEM_TOTAL);

    // ---- convert inputs to fp16 (x + 4 weights in 2 launches) ----
    const int NW = EE * EE;          // 1M
    const int NX = MM * EE;          // 4M
    cvt_f2h_kernel<<<NX / (256 * 8), 256>>>(x, xh, NX);
    dim3 wGrid(NW / (256 * 8), 4);
    cvt_w_kernel<<<wGrid, 256>>>(Wq, Wk, Wv, Wo, Wqh, Wkh, Wvh, Woh);

    // Q pre-scaled by 0.125 * log2(e) so softmax uses exp2 directly
    const float qscale = 0.18033688011112042f;

    // ---- merged Q/K/V projections (z selects target) ----
    dim3 qkvGrid(EE / 128, MM / 128, 3);   // (8, 32, 3)
    gemm_mma_kernel<<<qkvGrid, 256, GSMEM_TOTAL>>>(
        xh, Wqh, Wkh, Wvh, bq, bk, bv, nullptr, Qp, Kp, Vp, 1, qscale);

    // ---- attention ----
    dim3 faGrid(SS / 128, BB * HH);        // (16, 32)
    flash_mma_kernel<<<faGrid, dim3(256)>>>(Qp, Kp, Vp, Cp);

    // ---- output projection ----
    dim3 oGrid(EE / 128, MM / 128, 1);
    gemm_mma_kernel<<<oGrid, 256, GSMEM_TOTAL>>>(
        Cp, Woh, Woh, Woh, bo, bo, bo, out, nullptr, nullptr, nullptr, 0, 1.0f);
}